// round 13
// baseline (speedup 1.0000x reference)
#include <cuda_runtime.h>
#include <cuda_fp16.h>
#include <math.h>
#include <stdint.h>

#define N_TOK 4096
#define DIM   1024
#define FDIM  4096
#define NEXP  8

// ---------------------------------------------------------------------------
// Scratch (static device globals; no runtime allocation)
__device__ __half g_x_h[(size_t)N_TOK * DIM];
__device__ __half g_w1t[(size_t)NEXP * FDIM * DIM];   // [e][f][d]
__device__ __half g_w2t[(size_t)NEXP * DIM * FDIM];   // [e][d][f]
__device__ __half g_h[(size_t)2 * N_TOK * FDIM];      // [slot*N_TOK+tok][f]
__device__ int   g_list[NEXP * N_TOK];
__device__ float g_listp[NEXP * N_TOK];
__device__ int   g_cnt[NEXP];
__device__ float g_tpe[NEXP];
__device__ float g_psum[NEXP];

// ---------------------------------------------------------------------------
// PTX helpers (sm_80-era only: cp.async, ldmatrix, mma.sync — valid on sm_100)
static __device__ __forceinline__ uint32_t smem_u32(const void* p) {
    uint32_t a;
    asm("{ .reg .u64 t; cvta.to.shared.u64 t, %1; cvt.u32.u64 %0, t; }" : "=r"(a) : "l"(p));
    return a;
}
static __device__ __forceinline__ void cp16(uint32_t dst, const void* src) {
    asm volatile("cp.async.cg.shared.global [%0], [%1], 16;" :: "r"(dst), "l"(src));
}
#define CP_COMMIT()  asm volatile("cp.async.commit_group;" ::: "memory")
#define CP_WAIT2()   asm volatile("cp.async.wait_group 2;" ::: "memory")

static __device__ __forceinline__ void ldsm4(uint32_t& r0, uint32_t& r1, uint32_t& r2,
                                             uint32_t& r3, uint32_t addr) {
    asm volatile("ldmatrix.sync.aligned.m8n8.x4.shared.b16 {%0,%1,%2,%3}, [%4];"
                 : "=r"(r0), "=r"(r1), "=r"(r2), "=r"(r3) : "r"(addr));
}
static __device__ __forceinline__ void mma16816(float* c, const uint32_t* a, const uint32_t* b) {
    asm volatile(
        "mma.sync.aligned.m16n8k16.row.col.f32.f16.f16.f32 "
        "{%0,%1,%2,%3}, {%4,%5,%6,%7}, {%8,%9}, {%0,%1,%2,%3};"
        : "+f"(c[0]), "+f"(c[1]), "+f"(c[2]), "+f"(c[3])
        : "r"(a[0]), "r"(a[1]), "r"(a[2]), "r"(a[3]), "r"(b[0]), "r"(b[1]));
}

// ---------------------------------------------------------------------------
__global__ void zero_kernel(float* __restrict__ out, int out_size) {
    const int n4 = out_size >> 2;
    int i = blockIdx.x * blockDim.x + threadIdx.x;
    if (i < n4) *(float4*)(out + 4 * (size_t)i) = make_float4(0.f, 0.f, 0.f, 0.f);
    if (blockIdx.x == 0 && threadIdx.x == 0) {
        for (int r = n4 * 4; r < out_size; r++) out[r] = 0.0f;
    }
    if (blockIdx.x == 0 && threadIdx.x < NEXP) {
        g_cnt[threadIdx.x]  = 0;
        g_tpe[threadIdx.x]  = 0.0f;
        g_psum[threadIdx.x] = 0.0f;
    }
}

// ---------------------------------------------------------------------------
// Gating (+ folded x -> fp16 conversion). Warp-shuffle reductions.
__global__ __launch_bounds__(128) void gate_kernel(const float* __restrict__ x,
                                                   const float* __restrict__ gw) {
    const int n = blockIdx.x;
    const int t = threadIdx.x;
    const int wid = t >> 5, lane = t & 31;
    float acc[NEXP];
#pragma unroll
    for (int e = 0; e < NEXP; e++) acc[e] = 0.0f;

    const float* xr = x + (size_t)n * DIM;
    __half* xh = g_x_h + (size_t)n * DIM;
    for (int i = t; i < DIM; i += 128) {
        float xv = xr[i];
        xh[i] = __float2half_rn(xv);              // folded split_x
        const float* g = gw + (size_t)i * NEXP;
#pragma unroll
        for (int e = 0; e < NEXP; e++) acc[e] += xv * g[e];
    }

    // warp tree
#pragma unroll
    for (int e = 0; e < NEXP; e++)
#pragma unroll
        for (int off = 16; off > 0; off >>= 1)
            acc[e] += __shfl_xor_sync(0xFFFFFFFFu, acc[e], off);

    __shared__ float red[4][NEXP];
    __shared__ float logits[NEXP];
    if (lane == 0)
#pragma unroll
        for (int e = 0; e < NEXP; e++) red[wid][e] = acc[e];
    __syncthreads();
    if (t < NEXP) logits[t] = red[0][t] + red[1][t] + red[2][t] + red[3][t];
    __syncthreads();

    if (t == 0) {
        float mx = logits[0];
#pragma unroll
        for (int e = 1; e < NEXP; e++) mx = fmaxf(mx, logits[e]);
        float p[NEXP];
        float s = 0.0f;
#pragma unroll
        for (int e = 0; e < NEXP; e++) { p[e] = expf(logits[e] - mx); s += p[e]; }
        float inv = 1.0f / s;
#pragma unroll
        for (int e = 0; e < NEXP; e++) {
            p[e] *= inv;
            atomicAdd(&g_psum[e], p[e]);
        }
        int i0 = 0;
#pragma unroll
        for (int e = 1; e < NEXP; e++) if (p[e] > p[i0]) i0 = e;
        int i1 = (i0 == 0) ? 1 : 0;
#pragma unroll
        for (int e = 0; e < NEXP; e++) {
            if (e == i0) continue;
            if (p[e] > p[i1]) i1 = e;
        }
        float ssum = p[i0] + p[i1];
        float pn0 = p[i0] / (ssum + 1e-8f);
        float pn1 = p[i1] / (ssum + 1e-8f);
        atomicAdd(&g_tpe[i0], pn0);
        atomicAdd(&g_tpe[i1], pn1);
        int pos0 = atomicAdd(&g_cnt[i0], 1);
        g_list[i0 * N_TOK + pos0]  = n * 2 + 0;
        g_listp[i0 * N_TOK + pos0] = pn0;
        int pos1 = atomicAdd(&g_cnt[i1], 1);
        g_list[i1 * N_TOK + pos1]  = n * 2 + 1;
        g_listp[i1 * N_TOK + pos1] = pn1;
    }
}

// ---------------------------------------------------------------------------
// Fused weight transpose+convert: w1 [E][D][F] -> g_w1t [E][F][D] fp16,
//                                 w2 [E][F][D] -> g_w2t [E][D][F] fp16.
// One 1-D grid; first 8192 blocks do w1 tiles, next 8192 do w2.
// Tile 64(R) x 64(C), 256 threads, 4 float4 loads/thread (deep MLP).
__global__ __launch_bounds__(256) void convert_w_kernel(const float* __restrict__ w1,
                                                        const float* __restrict__ w2) {
    __shared__ float tile[64][65];
    int id = blockIdx.x;
    const float* w;
    __half* o;
    int R, C, bx, by, e;
    if (id < 8192) {
        w = w1; o = g_w1t; R = DIM;  C = FDIM;
        bx = id & 63; by = (id >> 6) & 15; e = id >> 10;
    } else {
        id -= 8192;
        w = w2; o = g_w2t; R = FDIM; C = DIM;
        bx = id & 15; by = (id >> 4) & 63; e = id >> 10;
    }
    const int r0 = by * 64, c0 = bx * 64;
    const int t = threadIdx.x;

    const int lr  = t >> 2;            // 0..63
    const int lcq = (t & 3) * 16;      // 0,16,32,48
    const float* src = w + ((size_t)e * R + (size_t)(r0 + lr)) * C + c0 + lcq;
    float4 v0 = *(const float4*)(src + 0);
    float4 v1 = *(const float4*)(src + 4);
    float4 v2 = *(const float4*)(src + 8);
    float4 v3 = *(const float4*)(src + 12);
    tile[lcq +  0][lr] = v0.x; tile[lcq +  1][lr] = v0.y;
    tile[lcq +  2][lr] = v0.z; tile[lcq +  3][lr] = v0.w;
    tile[lcq +  4][lr] = v1.x; tile[lcq +  5][lr] = v1.y;
    tile[lcq +  6][lr] = v1.z; tile[lcq +  7][lr] = v1.w;
    tile[lcq +  8][lr] = v2.x; tile[lcq +  9][lr] = v2.y;
    tile[lcq + 10][lr] = v2.z; tile[lcq + 11][lr] = v2.w;
    tile[lcq + 12][lr] = v3.x; tile[lcq + 13][lr] = v3.y;
    tile[lcq + 14][lr] = v3.z; tile[lcq + 15][lr] = v3.w;
    __syncthreads();

    const int lc  = t >> 2;            // 0..63
    const int lrq = (t & 3) * 16;      // 0,16,32,48
    __align__(16) __half h[16];
#pragma unroll
    for (int i = 0; i < 16; i++) h[i] = __float2half_rn(tile[lc][lrq + i]);
    const size_t ob = ((size_t)e * C + (size_t)(c0 + lc)) * R + r0 + lrq;
    *(uint4*)(o + ob)     = *(const uint4*)(h);
    *(uint4*)(o + ob + 8) = *(const uint4*)(h + 8);
}

// ---------------------------------------------------------------------------
// Grouped GEMM via warp-level fp16 HMMA, single pass (fp32 accumulate).
// CTA tile M=128 x N=128, K chunk = 64, 3-stage cp.async pipeline, 2 CTAs/SM.
// KSPLIT > 1 (GEMM2): blockIdx.x = kz * (NG/128) + n-block; each CTA covers
// K range [kz*KTOT/KSPLIT, ...); epilogue atomicAdd, bias only on kz==0.
#define OFF_ROWS  64u
#define OFF_PROBS 576u
#define OFF_BUF   2048u
#define B_OFF     16384u
#define STAGE_SZ  32768u
#define SMEM_BYTES (OFF_BUF + 3 * STAGE_SZ)

static __device__ __forceinline__ void prefetch_chunk(
    uint32_t sbuf, int k0,
    const __half* pa, const __half* pb, const uint32_t* dst) {
#pragma unroll
    for (int j = 0; j < 4; j++) cp16(sbuf +         dst[j], pa + k0 + j * 8);
#pragma unroll
    for (int j = 0; j < 4; j++) cp16(sbuf + B_OFF + dst[j], pb + k0 + j * 8);
}

template<int KTOT, int NG, bool PHASE2, int KSPLIT>
__global__ __launch_bounds__(256, 2) void moe_gemm(const float* __restrict__ bias,
                                                   float* __restrict__ out) {
    constexpr int KLOC   = KTOT / KSPLIT;
    constexpr int NCHUNK = KLOC / 64;
    constexpr int NBLK   = NG / 128;
    extern __shared__ char smem[];

    const int e = blockIdx.z;
    const int count = g_cnt[e];
    const int m0 = blockIdx.y * 128;
    if (m0 >= count) return;
    const int kz = (int)blockIdx.x / NBLK;
    const int n0 = ((int)blockIdx.x % NBLK) * 128;
    const int koff = kz * KLOC;
    const int tid = threadIdx.x;
    const int wid = tid >> 5, lane = tid & 31;
    const int warp_m = wid & 1;       // 0..1 -> 64-row block
    const int warp_n = wid >> 1;      // 0..3 -> 32-col block
    const uint32_t sbase = smem_u32(smem);

    int*   rows_s  = (int*)(smem + OFF_ROWS);
    float* probs_s = (float*)(smem + OFF_PROBS);
    if (tid < 128) {
        int m = m0 + tid;
        int idx = e * N_TOK + (m < count ? m : count - 1);
        rows_s[tid]  = g_list[idx];
        probs_s[tid] = g_listp[idx];
    }
    __syncthreads();

    // ---- gather/load geometry (identical to store-side swizzle) ----
    const int arow = tid >> 1;
    const int coff = (tid & 1) * 32;
    const int packed = rows_s[arow];
    size_t abase;
    if (PHASE2) abase = ((size_t)(packed & 1) * N_TOK + (size_t)(packed >> 1)) * (size_t)KTOT;
    else        abase = (size_t)(packed >> 1) * (size_t)KTOT;
    const __half* Asrc = PHASE2 ? g_h : g_x_h;
    const __half* Bsrc = PHASE2 ? g_w2t : g_w1t;
    const __half* pa = Asrc + abase + koff + coff;
    const __half* pb = Bsrc + ((size_t)e * NG + (size_t)(n0 + arow)) * (size_t)KTOT + koff + coff;

    uint32_t dst[4];
#pragma unroll
    for (int j = 0; j < 4; j++) {
        int c16 = (tid & 1) * 4 + j;
        dst[j] = (uint32_t)(arow * 128 + ((c16 ^ (arow & 7)) * 16));
    }

    // ---- ldmatrix address components ----
    const int a_r  = lane & 15;
    const int a_kb = lane >> 4;
    const int b_r  = (lane & 7) + ((lane >> 4) << 3);
    const int b_kb = (lane >> 3) & 1;

    float acc[4][4][4];
#pragma unroll
    for (int i = 0; i < 4; i++)
#pragma unroll
        for (int j = 0; j < 4; j++)
#pragma unroll
            for (int q = 0; q < 4; q++) acc[i][j][q] = 0.0f;

    // Prologue: prefetch chunks 0,1
    prefetch_chunk(sbase + OFF_BUF + 0 * STAGE_SZ, 0,  pa, pb, dst);
    CP_COMMIT();
    prefetch_chunk(sbase + OFF_BUF + 1 * STAGE_SZ, 64, pa, pb, dst);
    CP_COMMIT();

    for (int c = 0; c < NCHUNK; c++) {
        if (c + 2 < NCHUNK)
            prefetch_chunk(sbase + OFF_BUF + (uint32_t)((c + 2) % 3) * STAGE_SZ, (c + 2) * 64,
                           pa, pb, dst);
        CP_COMMIT();
        CP_WAIT2();
        __syncthreads();

        const uint32_t sA = sbase + OFF_BUF + (uint32_t)(c % 3) * STAGE_SZ;
        const uint32_t sB = sA + B_OFF;

#pragma unroll
        for (int ks = 0; ks < 4; ks++) {
            uint32_t ah[4][4], bh[4][2];
#pragma unroll
            for (int mf = 0; mf < 4; mf++) {
                int row = warp_m * 64 + mf * 16 + a_r;
                uint32_t off = (uint32_t)(row * 128 + (((2 * ks + a_kb) ^ (row & 7)) << 4));
                ldsm4(ah[mf][0], ah[mf][1], ah[mf][2], ah[mf][3], sA + off);
            }
#pragma unroll
            for (int np = 0; np < 2; np++) {
                int row = warp_n * 32 + np * 16 + b_r;
                uint32_t off = (uint32_t)(row * 128 + (((2 * ks + b_kb) ^ (row & 7)) << 4));
                ldsm4(bh[2 * np][0], bh[2 * np][1], bh[2 * np + 1][0], bh[2 * np + 1][1], sB + off);
            }
#pragma unroll
            for (int mf = 0; mf < 4; mf++)
#pragma unroll
                for (int nf = 0; nf < 4; nf++) mma16816(acc[mf][nf], ah[mf], bh[nf]);
        }
        __syncthreads();
    }

    // ---- epilogue ----
#pragma unroll
    for (int mf = 0; mf < 4; mf++) {
#pragma unroll
        for (int rr = 0; rr < 2; rr++) {
            const int row = warp_m * 64 + mf * 16 + (lane >> 2) + rr * 8;   // 0..127
            const int m = m0 + row;
            if (m >= count) continue;
            const int pk = rows_s[row];
            if (!PHASE2) {
                const int tok = pk >> 1, slot = pk & 1;
                const size_t hb = ((size_t)slot * N_TOK + (size_t)tok) * FDIM;
#pragma unroll
                for (int nf = 0; nf < 4; nf++) {
#pragma unroll
                    for (int jj = 0; jj < 2; jj++) {
                        const int col = n0 + warp_n * 32 + nf * 8 + 2 * (lane & 3) + jj;
                        float h = acc[mf][nf][rr * 2 + jj] + bias[(size_t)e * NG + col];
                        h = 0.5f * h * (1.0f + erff(h * 0.70710678118654752f));
                        g_h[hb + col] = __float2half_rn(h);
                    }
                }
            } else {
                const int tok = pk >> 1;
                const float prob = probs_s[row];
                float* orow = out + (size_t)tok * DIM;
#pragma unroll
                for (int nf = 0; nf < 4; nf++) {
#pragma unroll
                    for (int jj = 0; jj < 2; jj++) {
                        const int col = n0 + warp_n * 32 + nf * 8 + 2 * (lane & 3) + jj;
                        float v = acc[mf][nf][rr * 2 + jj];
                        if (kz == 0) v += bias[(size_t)e * NG + col];
                        atomicAdd(orow + col, v * prob);
                    }
                }
            }
        }
    }
}

// ---------------------------------------------------------------------------
__global__ void finalize_kernel(float* __restrict__ out, int out_size) {
    if (out_size <= N_TOK * DIM) return;
    float s = 0.0f;
#pragma unroll
    for (int e = 0; e < NEXP; e++) s += g_tpe[e];
    float loss = 0.0f;
#pragma unroll
    for (int e = 0; e < NEXP; e++)
        loss += g_tpe[e] / (s + 1e-8f) * (g_psum[e] / (float)N_TOK);
    loss *= (float)NEXP;
    out[N_TOK * DIM] = loss;
}

// ---------------------------------------------------------------------------
extern "C" void kernel_launch(void* const* d_in, const int* in_sizes, int n_in,
                              void* d_out, int out_size) {
    const float* x   = (const float*)d_in[0];
    const float* gw  = (const float*)d_in[1];
    const float* w1  = (const float*)d_in[2];
    const float* b1  = (const float*)d_in[3];
    const float* w2  = (const float*)d_in[4];
    const float* b2  = (const float*)d_in[5];
    float* out = (float*)d_out;

    cudaFuncSetAttribute(moe_gemm<DIM, FDIM, false, 1>,
                         cudaFuncAttributeMaxDynamicSharedMemorySize, SMEM_BYTES);
    cudaFuncSetAttribute(moe_gemm<FDIM, DIM, true, 4>,
                         cudaFuncAttributeMaxDynamicSharedMemorySize, SMEM_BYTES);

    zero_kernel<<<((out_size >> 2) + 255) / 256, 256>>>(out, out_size);
    gate_kernel<<<N_TOK, 128>>>(x, gw);
    convert_w_kernel<<<16384, 256>>>(w1, w2);
    moe_gemm<DIM, FDIM, false, 1><<<dim3(FDIM / 128, N_TOK / 128, NEXP), 256, SMEM_BYTES>>>(b1, out);
    moe_gemm<FDIM, DIM, true, 4><<<dim3(4 * DIM / 128, N_TOK / 128, NEXP), 256, SMEM_BYTES>>>(b2, out);
    finalize_kernel<<<1, 1>>>(out, out_size);
}

// round 14
// speedup vs baseline: 1.4624x; 1.4624x over previous
#include <cuda_runtime.h>
#include <cuda_fp16.h>
#include <math.h>
#include <stdint.h>

#define N_TOK 4096
#define DIM   1024
#define FDIM  4096
#define NEXP  8
#define MT_MAX (N_TOK / 128)   // 32 m-tiles per expert

// ---------------------------------------------------------------------------
// Scratch (static device globals; no runtime allocation)
// Packed, pre-swizzled, chunk-major operand buffers:
//   g_xp : A for GEMM1. [e][mt][kc(=d/64)][row 0..127][64] fp16, 16B groups
//          XOR-permuted by (row&7). One (mt,kc) chunk = 16KB contiguous.
//   g_hp : A for GEMM2 (gelu outputs), same scheme with kc = f/64.
//   g_w1t: B for GEMM1. [e][kc(=d/64)][f][64], groups permuted by (f&7).
//   g_w2t: B for GEMM2. [e][kc(=f/64)][d][64], groups permuted by (d&7).
__device__ __half g_xp [(size_t)NEXP * N_TOK * DIM];
__device__ __half g_hp [(size_t)NEXP * N_TOK * FDIM];
__device__ __half g_w1t[(size_t)NEXP * FDIM * DIM];
__device__ __half g_w2t[(size_t)NEXP * DIM * FDIM];
__device__ int   g_list[NEXP * N_TOK];
__device__ float g_listp[NEXP * N_TOK];
__device__ int   g_cnt[NEXP];
__device__ float g_tpe[NEXP];
__device__ float g_psum[NEXP];

// ---------------------------------------------------------------------------
// PTX helpers (sm_90-era max: cp.async.bulk, mbarrier, ldmatrix, mma.sync)
static __device__ __forceinline__ uint32_t smem_u32(const void* p) {
    uint32_t a;
    asm("{ .reg .u64 t; cvta.to.shared.u64 t, %1; cvt.u32.u64 %0, t; }" : "=r"(a) : "l"(p));
    return a;
}
static __device__ __forceinline__ void tma_bulk(uint32_t dst, const void* src,
                                                uint32_t bytes, uint32_t mbar) {
    asm volatile(
        "cp.async.bulk.shared::cluster.global.mbarrier::complete_tx::bytes [%0], [%1], %2, [%3];"
        :: "r"(dst), "l"(src), "r"(bytes), "r"(mbar) : "memory");
}
static __device__ __forceinline__ void mbar_init(uint32_t a, uint32_t cnt) {
    asm volatile("mbarrier.init.shared.b64 [%0], %1;" :: "r"(a), "r"(cnt) : "memory");
}
static __device__ __forceinline__ void mbar_expect(uint32_t a, uint32_t bytes) {
    asm volatile("mbarrier.arrive.expect_tx.shared.b64 _, [%0], %1;"
                 :: "r"(a), "r"(bytes) : "memory");
}
static __device__ __forceinline__ void mbar_wait(uint32_t a, uint32_t parity) {
    asm volatile(
        "{\n\t.reg .pred P;\n\t"
        "LW%=:\n\t"
        "mbarrier.try_wait.parity.shared.b64 P, [%0], %1;\n\t"
        "@!P bra LW%=;\n\t}"
        :: "r"(a), "r"(parity) : "memory");
}
static __device__ __forceinline__ void ldsm4(uint32_t& r0, uint32_t& r1, uint32_t& r2,
                                             uint32_t& r3, uint32_t addr) {
    asm volatile("ldmatrix.sync.aligned.m8n8.x4.shared.b16 {%0,%1,%2,%3}, [%4];"
                 : "=r"(r0), "=r"(r1), "=r"(r2), "=r"(r3) : "r"(addr));
}
static __device__ __forceinline__ void mma16816(float* c, const uint32_t* a, const uint32_t* b) {
    asm volatile(
        "mma.sync.aligned.m16n8k16.row.col.f32.f16.f16.f32 "
        "{%0,%1,%2,%3}, {%4,%5,%6,%7}, {%8,%9}, {%0,%1,%2,%3};"
        : "+f"(c[0]), "+f"(c[1]), "+f"(c[2]), "+f"(c[3])
        : "r"(a[0]), "r"(a[1]), "r"(a[2]), "r"(a[3]), "r"(b[0]), "r"(b[1]));
}

// ---------------------------------------------------------------------------
__global__ void zero_kernel(float* __restrict__ out, int out_size) {
    const int n4 = out_size >> 2;
    int i = blockIdx.x * blockDim.x + threadIdx.x;
    if (i < n4) *(float4*)(out + 4 * (size_t)i) = make_float4(0.f, 0.f, 0.f, 0.f);
    if (blockIdx.x == 0 && threadIdx.x == 0) {
        for (int r = n4 * 4; r < out_size; r++) out[r] = 0.0f;
    }
    if (blockIdx.x == 0 && threadIdx.x < NEXP) {
        g_cnt[threadIdx.x]  = 0;
        g_tpe[threadIdx.x]  = 0.0f;
        g_psum[threadIdx.x] = 0.0f;
    }
}

// ---------------------------------------------------------------------------
// Gating + packed-A construction. After top-2 selection, the block writes its
// token's x row (fp16) into both selected experts' packed chunk-major buffers
// with the 16B-group XOR swizzle by (list_pos & 7).
__global__ __launch_bounds__(128) void gate_kernel(const float* __restrict__ x,
                                                   const float* __restrict__ gw) {
    const int n = blockIdx.x;
    const int t = threadIdx.x;
    const int wid = t >> 5, lane = t & 31;
    float acc[NEXP];
#pragma unroll
    for (int e = 0; e < NEXP; e++) acc[e] = 0.0f;

    const float* xr = x + (size_t)n * DIM;
    for (int i = t; i < DIM; i += 128) {
        float xv = xr[i];
        const float* g = gw + (size_t)i * NEXP;
#pragma unroll
        for (int e = 0; e < NEXP; e++) acc[e] += xv * g[e];
    }

#pragma unroll
    for (int e = 0; e < NEXP; e++)
#pragma unroll
        for (int off = 16; off > 0; off >>= 1)
            acc[e] += __shfl_xor_sync(0xFFFFFFFFu, acc[e], off);

    __shared__ float red[4][NEXP];
    __shared__ float logits[NEXP];
    __shared__ int   sel[4];   // e0, pos0, e1, pos1
    if (lane == 0)
#pragma unroll
        for (int e = 0; e < NEXP; e++) red[wid][e] = acc[e];
    __syncthreads();
    if (t < NEXP) logits[t] = red[0][t] + red[1][t] + red[2][t] + red[3][t];
    __syncthreads();

    if (t == 0) {
        float mx = logits[0];
#pragma unroll
        for (int e = 1; e < NEXP; e++) mx = fmaxf(mx, logits[e]);
        float p[NEXP];
        float s = 0.0f;
#pragma unroll
        for (int e = 0; e < NEXP; e++) { p[e] = expf(logits[e] - mx); s += p[e]; }
        float inv = 1.0f / s;
#pragma unroll
        for (int e = 0; e < NEXP; e++) {
            p[e] *= inv;
            atomicAdd(&g_psum[e], p[e]);
        }
        int i0 = 0;
#pragma unroll
        for (int e = 1; e < NEXP; e++) if (p[e] > p[i0]) i0 = e;
        int i1 = (i0 == 0) ? 1 : 0;
#pragma unroll
        for (int e = 0; e < NEXP; e++) {
            if (e == i0) continue;
            if (p[e] > p[i1]) i1 = e;
        }
        float ssum = p[i0] + p[i1];
        float pn0 = p[i0] / (ssum + 1e-8f);
        float pn1 = p[i1] / (ssum + 1e-8f);
        atomicAdd(&g_tpe[i0], pn0);
        atomicAdd(&g_tpe[i1], pn1);
        int pos0 = atomicAdd(&g_cnt[i0], 1);
        g_list[i0 * N_TOK + pos0]  = n * 2 + 0;
        g_listp[i0 * N_TOK + pos0] = pn0;
        int pos1 = atomicAdd(&g_cnt[i1], 1);
        g_list[i1 * N_TOK + pos1]  = n * 2 + 1;
        g_listp[i1 * N_TOK + pos1] = pn1;
        sel[0] = i0; sel[1] = pos0; sel[2] = i1; sel[3] = pos1;
    }
    __syncthreads();

    // Pack this token's row: thread t owns 16B group t (elems t*8 .. t*8+7).
    __align__(16) __half hv[8];
    const float* xs = xr + t * 8;
#pragma unroll
    for (int i = 0; i < 8; i++) hv[i] = __float2half_rn(xs[i]);
    const uint4 pk = *(const uint4*)hv;
    const int kc = t >> 3, g = t & 7;
#pragma unroll
    for (int w = 0; w < 2; w++) {
        const int e = sel[2 * w], pos = sel[2 * w + 1];
        const int mt = pos >> 7, r = pos & 127;
        size_t off = ((((size_t)e * MT_MAX + mt) * (DIM / 64) + kc) * 128 + r) * 64
                     + (size_t)((g ^ (r & 7)) * 8);
        *(uint4*)(g_xp + off) = pk;
    }
}

// ---------------------------------------------------------------------------
// Weight transpose + convert + chunk-major pack + pre-swizzle.
// w1 [E][D][F] -> g_w1t [e][kc=d/64][f][64] ; w2 [E][F][D] -> g_w2t [e][kc=f/64][d][64]
// 16B groups within each 64-elem row permuted by (n&7) (n = output row index).
__global__ __launch_bounds__(256) void convert_w_kernel(const float* __restrict__ w1,
                                                        const float* __restrict__ w2) {
    __shared__ float tile[64][65];
    int id = blockIdx.x;
    const float* w;
    __half* o;
    int R, C, bx, by, e;
    if (id < 8192) {
        w = w1; o = g_w1t; R = DIM;  C = FDIM;
        bx = id & 63; by = (id >> 6) & 15; e = id >> 10;
    } else {
        id -= 8192;
        w = w2; o = g_w2t; R = FDIM; C = DIM;
        bx = id & 15; by = (id >> 4) & 63; e = id >> 10;
    }
    const int r0 = by * 64, c0 = bx * 64;
    const int t = threadIdx.x;

    const int lr  = t >> 2;            // 0..63 (K rows)
    const int lcq = (t & 3) * 16;      // 0,16,32,48 (N cols)
    const float* src = w + ((size_t)e * R + (size_t)(r0 + lr)) * C + c0 + lcq;
    float4 v0 = *(const float4*)(src + 0);
    float4 v1 = *(const float4*)(src + 4);
    float4 v2 = *(const float4*)(src + 8);
    float4 v3 = *(const float4*)(src + 12);
    tile[lcq +  0][lr] = v0.x; tile[lcq +  1][lr] = v0.y;
    tile[lcq +  2][lr] = v0.z; tile[lcq +  3][lr] = v0.w;
    tile[lcq +  4][lr] = v1.x; tile[lcq +  5][lr] = v1.y;
    tile[lcq +  6][lr] = v1.z; tile[lcq +  7][lr] = v1.w;
    tile[lcq +  8][lr] = v2.x; tile[lcq +  9][lr] = v2.y;
    tile[lcq + 10][lr] = v2.z; tile[lcq + 11][lr] = v2.w;
    tile[lcq + 12][lr] = v3.x; tile[lcq + 13][lr] = v3.y;
    tile[lcq + 14][lr] = v3.z; tile[lcq + 15][lr] = v3.w;
    __syncthreads();

    const int lc  = t >> 2;            // output row n (0..63 local)
    const int lrq = (t & 3) * 16;      // K offset within the 64-block: 0,16,32,48
    const int n   = c0 + lc;
    const int kc  = r0 >> 6;           // r0 is 64-aligned
    const int KCH = R / 64;
    __align__(16) __half h[16];
#pragma unroll
    for (int i = 0; i < 16; i++) h[i] = __float2half_rn(tile[lc][lrq + i]);
    const size_t base = (((size_t)e * KCH + kc) * (size_t)C + n) * 64;
    const int g0 = lrq >> 3;           // 16B-group index (even)
    *(uint4*)(o + base + ((g0       ^ (n & 7)) << 3)) = *(const uint4*)(h);
    *(uint4*)(o + base + (((g0 + 1) ^ (n & 7)) << 3)) = *(const uint4*)(h + 8);
}

// ---------------------------------------------------------------------------
// Grouped GEMM, fp16 HMMA, fp32 accum. CTA tile 128x128, K chunk 64.
// Loads: TWO cp.async.bulk 16KB copies per chunk (A + B), both pre-swizzled
// chunk-major in gmem -> flat 128B-pitch smem, mbarrier-paced 3-stage pipeline,
// ONE __syncthreads per chunk. 2 CTAs/SM.
#define OFF_MBAR  16u
#define OFF_ROWS  64u
#define OFF_PROBS 576u
#define OFF_BUF   2048u
#define B_OFF     16384u
#define STAGE_SZ  32768u
#define SMEM_BYTES (OFF_BUF + 3 * STAGE_SZ)

template<int KTOT, int NG, bool PHASE2, int KSPLIT>
__global__ __launch_bounds__(256, 2) void moe_gemm(const float* __restrict__ bias,
                                                   float* __restrict__ out) {
    constexpr int KCH    = KTOT / 64;
    constexpr int KLOC   = KTOT / KSPLIT;
    constexpr int NCHUNK = KLOC / 64;
    constexpr int NBLK   = NG / 128;
    extern __shared__ char smem[];

    const int e = blockIdx.z;
    const int count = g_cnt[e];
    const int mt = blockIdx.y;
    const int m0 = mt * 128;
    if (m0 >= count) return;
    const int kz = (int)blockIdx.x / NBLK;
    const int n0 = ((int)blockIdx.x % NBLK) * 128;
    const int kc0 = kz * NCHUNK;
    const int tid = threadIdx.x;
    const int wid = tid >> 5, lane = tid & 31;
    const int warp_m = wid & 1;
    const int warp_n = wid >> 1;
    const uint32_t sbase = smem_u32(smem);

    int*   rows_s  = (int*)(smem + OFF_ROWS);
    float* probs_s = (float*)(smem + OFF_PROBS);
    if (PHASE2 && tid < 128) {
        int m = m0 + tid;
        int idx = e * N_TOK + (m < count ? m : count - 1);
        rows_s[tid]  = g_list[idx];
        probs_s[tid] = g_listp[idx];
    }
    if (tid == 0) {
        mbar_init(sbase + OFF_MBAR + 0, 1);
        mbar_init(sbase + OFF_MBAR + 8, 1);
        mbar_init(sbase + OFF_MBAR + 16, 1);
    }
    __syncthreads();

    // Chunk-contiguous packed sources
    const __half* Ap = (PHASE2 ? g_hp : g_xp)
                     + (((size_t)e * MT_MAX + mt) * KCH + kc0) * 8192;   // 8192 elem / chunk
    const __half* Bp = (PHASE2 ? g_w2t : g_w1t)
                     + (((size_t)e * KCH + kc0) * (size_t)NG + n0) * 64;

    auto issue = [&](int c) {
        const uint32_t mb = sbase + OFF_MBAR + (uint32_t)(c % 3) * 8;
        const uint32_t st = sbase + OFF_BUF + (uint32_t)(c % 3) * STAGE_SZ;
        mbar_expect(mb, 32768);
        tma_bulk(st,         Ap + (size_t)c * 8192,            16384, mb);
        tma_bulk(st + B_OFF, Bp + (size_t)c * (size_t)NG * 64, 16384, mb);
    };
    if (tid == 0) {
        issue(0);
        if (NCHUNK > 1) issue(1);
    }

    const int a_r  = lane & 15;
    const int a_kb = lane >> 4;
    const int b_r  = (lane & 7) + ((lane >> 4) << 3);
    const int b_kb = (lane >> 3) & 1;

    float acc[4][4][4];
#pragma unroll
    for (int i = 0; i < 4; i++)
#pragma unroll
        for (int j = 0; j < 4; j++)
#pragma unroll
            for (int q = 0; q < 4; q++) acc[i][j][q] = 0.0f;

    for (int c = 0; c < NCHUNK; c++) {
        const int s = c % 3;
        mbar_wait(sbase + OFF_MBAR + (uint32_t)s * 8, (uint32_t)((c / 3) & 1));
        __syncthreads();   // all warps done with chunk c-1; safe to refill its stage
        if (tid == 0 && c + 2 < NCHUNK) issue(c + 2);

        const uint32_t sA = sbase + OFF_BUF + (uint32_t)s * STAGE_SZ;
        const uint32_t sB = sA + B_OFF;

#pragma unroll
        for (int ks = 0; ks < 4; ks++) {
            uint32_t ah[4][4], bh[4][2];
#pragma unroll
            for (int mf = 0; mf < 4; mf++) {
                int row = warp_m * 64 + mf * 16 + a_r;
                uint32_t off = (uint32_t)(row * 128 + (((2 * ks + a_kb) ^ (row & 7)) << 4));
                ldsm4(ah[mf][0], ah[mf][1], ah[mf][2], ah[mf][3], sA + off);
            }
#pragma unroll
            for (int np = 0; np < 2; np++) {
                int row = warp_n * 32 + np * 16 + b_r;
                uint32_t off = (uint32_t)(row * 128 + (((2 * ks + b_kb) ^ (row & 7)) << 4));
                ldsm4(bh[2 * np][0], bh[2 * np][1], bh[2 * np + 1][0], bh[2 * np + 1][1], sB + off);
            }
#pragma unroll
            for (int mf = 0; mf < 4; mf++)
#pragma unroll
                for (int nf = 0; nf < 4; nf++) mma16816(acc[mf][nf], ah[mf], bh[nf]);
        }
    }

    // ---- epilogue ----
#pragma unroll
    for (int mf = 0; mf < 4; mf++) {
#pragma unroll
        for (int rr = 0; rr < 2; rr++) {
            const int row = warp_m * 64 + mf * 16 + (lane >> 2) + rr * 8;   // 0..127
            const int m = m0 + row;
            if (m >= count) continue;
            if (!PHASE2) {
                // write h (gelu) into g_hp packed layout for GEMM2
#pragma unroll
                for (int nf = 0; nf < 4; nf++) {
                    const int cp = n0 + warp_n * 32 + nf * 8 + 2 * (lane & 3);
                    float h0 = acc[mf][nf][rr * 2 + 0] + bias[(size_t)e * NG + cp];
                    float h1 = acc[mf][nf][rr * 2 + 1] + bias[(size_t)e * NG + cp + 1];
                    h0 = 0.5f * h0 * (1.0f + erff(h0 * 0.70710678118654752f));
                    h1 = 0.5f * h1 * (1.0f + erff(h1 * 0.70710678118654752f));
                    const int kc2 = cp >> 6, g = (cp & 63) >> 3, gi = cp & 7;
                    size_t off = ((((size_t)e * MT_MAX + mt) * (FDIM / 64) + kc2) * 128 + row) * 64
                               + (size_t)((g ^ (row & 7)) * 8 + gi);
                    *(__half2*)(g_hp + off) = __floats2half2_rn(h0, h1);
                }
            } else {
                const int pk = rows_s[row];
                const int tok = pk >> 1;
                const float prob = probs_s[row];
                float* orow = out + (size_t)tok * DIM;
#pragma unroll
                for (int nf = 0; nf < 4; nf++) {
#pragma unroll
                    for (int jj = 0; jj < 2; jj++) {
                        const int col = n0 + warp_n * 32 + nf * 8 + 2 * (lane & 3) + jj;
                        float v = acc[mf][nf][rr * 2 + jj];
                        if (kz == 0) v += bias[(size_t)e * NG + col];
                        atomicAdd(orow + col, v * prob);
                    }
                }
            }
        }
    }
}

// ---------------------------------------------------------------------------
__global__ void finalize_kernel(float* __restrict__ out, int out_size) {
    if (out_size <= N_TOK * DIM) return;
    float s = 0.0f;
#pragma unroll
    for (int e = 0; e < NEXP; e++) s += g_tpe[e];
    float loss = 0.0f;
#pragma unroll
    for (int e = 0; e < NEXP; e++)
        loss += g_tpe[e] / (s + 1e-8f) * (g_psum[e] / (float)N_TOK);
    loss *= (float)NEXP;
    out[N_TOK * DIM] = loss;
}

// ---------------------------------------------------------------------------
extern "C" void kernel_launch(void* const* d_in, const int* in_sizes, int n_in,
                              void* d_out, int out_size) {
    const float* x   = (const float*)d_in[0];
    const float* gw  = (const float*)d_in[1];
    const float* w1  = (const float*)d_in[2];
    const float* b1  = (const float*)d_in[3];
    const float* w2  = (const float*)d_in[4];
    const float* b2  = (const float*)d_in[5];
    float* out = (float*)d_out;

    cudaFuncSetAttribute(moe_gemm<DIM, FDIM, false, 1>,
                         cudaFuncAttributeMaxDynamicSharedMemorySize, SMEM_BYTES);
    cudaFuncSetAttribute(moe_gemm<FDIM, DIM, true, 4>,
                         cudaFuncAttributeMaxDynamicSharedMemorySize, SMEM_BYTES);

    zero_kernel<<<((out_size >> 2) + 255) / 256, 256>>>(out, out_size);
    gate_kernel<<<N_TOK, 128>>>(x, gw);
    convert_w_kernel<<<16384, 256>>>(w1, w2);
    moe_gemm<DIM, FDIM, false, 1><<<dim3(FDIM / 128, MT_MAX, NEXP), 256, SMEM_BYTES>>>(b1, out);
    moe_gemm<FDIM, DIM, true, 4><<<dim3(4 * DIM / 128, MT_MAX, NEXP), 256, SMEM_BYTES>>>(b2, out);
    finalize_kernel<<<1, 1>>>(out, out_size);
}

// round 15
// speedup vs baseline: 1.4996x; 1.0255x over previous
#include <cuda_runtime.h>
#include <cuda_fp16.h>
#include <math.h>
#include <stdint.h>

#define N_TOK 4096
#define DIM   1024
#define FDIM  4096
#define NEXP  8
#define MT_MAX (N_TOK / 128)   // 32 m-tiles per expert

// ---------------------------------------------------------------------------
// Scratch (static device globals; no runtime allocation)
// Packed, pre-swizzled, chunk-major operand buffers:
//   g_xp : A for GEMM1. [e][mt][kc(=d/64)][row 0..127][64] fp16, 16B groups
//          XOR-permuted by (row&7). One (mt,kc) chunk = 16KB contiguous.
//   g_hp : A for GEMM2 (gelu outputs), same scheme with kc = f/64.
//   g_w1t: B for GEMM1. [e][kc(=d/64)][f][64], groups permuted by (f&7).
//   g_w2t: B for GEMM2. [e][kc(=f/64)][d][64], groups permuted by (d&7).
__device__ __half g_xp [(size_t)NEXP * N_TOK * DIM];
__device__ __half g_hp [(size_t)NEXP * N_TOK * FDIM];
__device__ __half g_w1t[(size_t)NEXP * FDIM * DIM];
__device__ __half g_w2t[(size_t)NEXP * DIM * FDIM];
__device__ int   g_list[NEXP * N_TOK];
__device__ float g_listp[NEXP * N_TOK];
__device__ int   g_cnt[NEXP];
__device__ float g_tpe[NEXP];
__device__ float g_psum[NEXP];

// ---------------------------------------------------------------------------
// PTX helpers (sm_90-era max: cp.async.bulk, mbarrier, ldmatrix, mma.sync)
static __device__ __forceinline__ uint32_t smem_u32(const void* p) {
    uint32_t a;
    asm("{ .reg .u64 t; cvta.to.shared.u64 t, %1; cvt.u32.u64 %0, t; }" : "=r"(a) : "l"(p));
    return a;
}
static __device__ __forceinline__ void tma_bulk(uint32_t dst, const void* src,
                                                uint32_t bytes, uint32_t mbar) {
    asm volatile(
        "cp.async.bulk.shared::cluster.global.mbarrier::complete_tx::bytes [%0], [%1], %2, [%3];"
        :: "r"(dst), "l"(src), "r"(bytes), "r"(mbar) : "memory");
}
static __device__ __forceinline__ void mbar_init(uint32_t a, uint32_t cnt) {
    asm volatile("mbarrier.init.shared.b64 [%0], %1;" :: "r"(a), "r"(cnt) : "memory");
}
static __device__ __forceinline__ void mbar_expect(uint32_t a, uint32_t bytes) {
    asm volatile("mbarrier.arrive.expect_tx.shared.b64 _, [%0], %1;"
                 :: "r"(a), "r"(bytes) : "memory");
}
static __device__ __forceinline__ void mbar_wait(uint32_t a, uint32_t parity) {
    asm volatile(
        "{\n\t.reg .pred P;\n\t"
        "LW%=:\n\t"
        "mbarrier.try_wait.parity.shared.b64 P, [%0], %1;\n\t"
        "@!P bra LW%=;\n\t}"
        :: "r"(a), "r"(parity) : "memory");
}
static __device__ __forceinline__ void ldsm4(uint32_t& r0, uint32_t& r1, uint32_t& r2,
                                             uint32_t& r3, uint32_t addr) {
    asm volatile("ldmatrix.sync.aligned.m8n8.x4.shared.b16 {%0,%1,%2,%3}, [%4];"
                 : "=r"(r0), "=r"(r1), "=r"(r2), "=r"(r3) : "r"(addr));
}
static __device__ __forceinline__ void mma16816(float* c, const uint32_t* a, const uint32_t* b) {
    asm volatile(
        "mma.sync.aligned.m16n8k16.row.col.f32.f16.f16.f32 "
        "{%0,%1,%2,%3}, {%4,%5,%6,%7}, {%8,%9}, {%0,%1,%2,%3};"
        : "+f"(c[0]), "+f"(c[1]), "+f"(c[2]), "+f"(c[3])
        : "r"(a[0]), "r"(a[1]), "r"(a[2]), "r"(a[3]), "r"(b[0]), "r"(b[1]));
}

// ---------------------------------------------------------------------------
__global__ void zero_kernel(float* __restrict__ out, int out_size) {
    const int n4 = out_size >> 2;
    int i = blockIdx.x * blockDim.x + threadIdx.x;
    if (i < n4) *(float4*)(out + 4 * (size_t)i) = make_float4(0.f, 0.f, 0.f, 0.f);
    if (blockIdx.x == 0 && threadIdx.x == 0) {
        for (int r = n4 * 4; r < out_size; r++) out[r] = 0.0f;
    }
    if (blockIdx.x == 0 && threadIdx.x < NEXP) {
        g_cnt[threadIdx.x]  = 0;
        g_tpe[threadIdx.x]  = 0.0f;
        g_psum[threadIdx.x] = 0.0f;
    }
}

// ---------------------------------------------------------------------------
// Gating + packed-A construction. After top-2 selection, the block writes its
// token's x row (fp16) into both selected experts' packed chunk-major buffers
// with the 16B-group XOR swizzle by (list_pos & 7).
__global__ __launch_bounds__(128) void gate_kernel(const float* __restrict__ x,
                                                   const float* __restrict__ gw) {
    const int n = blockIdx.x;
    const int t = threadIdx.x;
    const int wid = t >> 5, lane = t & 31;
    float acc[NEXP];
#pragma unroll
    for (int e = 0; e < NEXP; e++) acc[e] = 0.0f;

    const float* xr = x + (size_t)n * DIM;
    for (int i = t; i < DIM; i += 128) {
        float xv = xr[i];
        const float* g = gw + (size_t)i * NEXP;
#pragma unroll
        for (int e = 0; e < NEXP; e++) acc[e] += xv * g[e];
    }

#pragma unroll
    for (int e = 0; e < NEXP; e++)
#pragma unroll
        for (int off = 16; off > 0; off >>= 1)
            acc[e] += __shfl_xor_sync(0xFFFFFFFFu, acc[e], off);

    __shared__ float red[4][NEXP];
    __shared__ float logits[NEXP];
    __shared__ int   sel[4];   // e0, pos0, e1, pos1
    if (lane == 0)
#pragma unroll
        for (int e = 0; e < NEXP; e++) red[wid][e] = acc[e];
    __syncthreads();
    if (t < NEXP) logits[t] = red[0][t] + red[1][t] + red[2][t] + red[3][t];
    __syncthreads();

    if (t == 0) {
        float mx = logits[0];
#pragma unroll
        for (int e = 1; e < NEXP; e++) mx = fmaxf(mx, logits[e]);
        float p[NEXP];
        float s = 0.0f;
#pragma unroll
        for (int e = 0; e < NEXP; e++) { p[e] = expf(logits[e] - mx); s += p[e]; }
        float inv = 1.0f / s;
#pragma unroll
        for (int e = 0; e < NEXP; e++) {
            p[e] *= inv;
            atomicAdd(&g_psum[e], p[e]);
        }
        int i0 = 0;
#pragma unroll
        for (int e = 1; e < NEXP; e++) if (p[e] > p[i0]) i0 = e;
        int i1 = (i0 == 0) ? 1 : 0;
#pragma unroll
        for (int e = 0; e < NEXP; e++) {
            if (e == i0) continue;
            if (p[e] > p[i1]) i1 = e;
        }
        float ssum = p[i0] + p[i1];
        float pn0 = p[i0] / (ssum + 1e-8f);
        float pn1 = p[i1] / (ssum + 1e-8f);
        atomicAdd(&g_tpe[i0], pn0);
        atomicAdd(&g_tpe[i1], pn1);
        int pos0 = atomicAdd(&g_cnt[i0], 1);
        g_list[i0 * N_TOK + pos0]  = n * 2 + 0;
        g_listp[i0 * N_TOK + pos0] = pn0;
        int pos1 = atomicAdd(&g_cnt[i1], 1);
        g_list[i1 * N_TOK + pos1]  = n * 2 + 1;
        g_listp[i1 * N_TOK + pos1] = pn1;
        sel[0] = i0; sel[1] = pos0; sel[2] = i1; sel[3] = pos1;
    }
    __syncthreads();

    // Pack this token's row: thread t owns 16B group t (elems t*8 .. t*8+7).
    __align__(16) __half hv[8];
    const float* xs = xr + t * 8;
#pragma unroll
    for (int i = 0; i < 8; i++) hv[i] = __float2half_rn(xs[i]);
    const uint4 pk = *(const uint4*)hv;
    const int kc = t >> 3, g = t & 7;
#pragma unroll
    for (int w = 0; w < 2; w++) {
        const int e = sel[2 * w], pos = sel[2 * w + 1];
        const int mt = pos >> 7, r = pos & 127;
        size_t off = ((((size_t)e * MT_MAX + mt) * (DIM / 64) + kc) * 128 + r) * 64
                     + (size_t)((g ^ (r & 7)) * 8);
        *(uint4*)(g_xp + off) = pk;
    }
}

// ---------------------------------------------------------------------------
// Weight transpose + convert + chunk-major pack + pre-swizzle.
// w1 [E][D][F] -> g_w1t [e][kc=d/64][f][64] ; w2 [E][F][D] -> g_w2t [e][kc=f/64][d][64]
// 16B groups within each 64-elem row permuted by (n&7) (n = output row index).
__global__ __launch_bounds__(256) void convert_w_kernel(const float* __restrict__ w1,
                                                        const float* __restrict__ w2) {
    __shared__ float tile[64][65];
    int id = blockIdx.x;
    const float* w;
    __half* o;
    int R, C, bx, by, e;
    if (id < 8192) {
        w = w1; o = g_w1t; R = DIM;  C = FDIM;
        bx = id & 63; by = (id >> 6) & 15; e = id >> 10;
    } else {
        id -= 8192;
        w = w2; o = g_w2t; R = FDIM; C = DIM;
        bx = id & 15; by = (id >> 4) & 63; e = id >> 10;
    }
    const int r0 = by * 64, c0 = bx * 64;
    const int t = threadIdx.x;

    const int lr  = t >> 2;            // 0..63 (K rows)
    const int lcq = (t & 3) * 16;      // 0,16,32,48 (N cols)
    const float* src = w + ((size_t)e * R + (size_t)(r0 + lr)) * C + c0 + lcq;
    float4 v0 = *(const float4*)(src + 0);
    float4 v1 = *(const float4*)(src + 4);
    float4 v2 = *(const float4*)(src + 8);
    float4 v3 = *(const float4*)(src + 12);
    tile[lcq +  0][lr] = v0.x; tile[lcq +  1][lr] = v0.y;
    tile[lcq +  2][lr] = v0.z; tile[lcq +  3][lr] = v0.w;
    tile[lcq +  4][lr] = v1.x; tile[lcq +  5][lr] = v1.y;
    tile[lcq +  6][lr] = v1.z; tile[lcq +  7][lr] = v1.w;
    tile[lcq +  8][lr] = v2.x; tile[lcq +  9][lr] = v2.y;
    tile[lcq + 10][lr] = v2.z; tile[lcq + 11][lr] = v2.w;
    tile[lcq + 12][lr] = v3.x; tile[lcq + 13][lr] = v3.y;
    tile[lcq + 14][lr] = v3.z; tile[lcq + 15][lr] = v3.w;
    __syncthreads();

    const int lc  = t >> 2;            // output row n (0..63 local)
    const int lrq = (t & 3) * 16;      // K offset within the 64-block: 0,16,32,48
    const int n   = c0 + lc;
    const int kc  = r0 >> 6;           // r0 is 64-aligned
    const int KCH = R / 64;
    __align__(16) __half h[16];
#pragma unroll
    for (int i = 0; i < 16; i++) h[i] = __float2half_rn(tile[lc][lrq + i]);
    const size_t base = (((size_t)e * KCH + kc) * (size_t)C + n) * 64;
    const int g0 = lrq >> 3;           // 16B-group index (even)
    *(uint4*)(o + base + ((g0       ^ (n & 7)) << 3)) = *(const uint4*)(h);
    *(uint4*)(o + base + (((g0 + 1) ^ (n & 7)) << 3)) = *(const uint4*)(h + 8);
}

// ---------------------------------------------------------------------------
// Grouped GEMM, fp16 HMMA, fp32 accum. CTA tile 128x128, K chunk 64.
// 4 warps, warp tile 64x64 (8 LDSM feed 32 MMAs per ks-step).
// Loads: TWO cp.async.bulk 16KB copies per chunk (A + B), pre-swizzled
// chunk-major gmem -> flat 128B-pitch smem, mbarrier-paced 3-stage pipeline,
// one __syncthreads per chunk. 2 CTAs/SM.
#define OFF_MBAR  16u
#define OFF_ROWS  64u
#define OFF_PROBS 576u
#define OFF_BUF   2048u
#define B_OFF     16384u
#define STAGE_SZ  32768u
#define SMEM_BYTES (OFF_BUF + 3 * STAGE_SZ)

template<int KTOT, int NG, bool PHASE2, int KSPLIT>
__global__ __launch_bounds__(128, 2) void moe_gemm(const float* __restrict__ bias,
                                                   float* __restrict__ out) {
    constexpr int KCH    = KTOT / 64;
    constexpr int KLOC   = KTOT / KSPLIT;
    constexpr int NCHUNK = KLOC / 64;
    constexpr int NBLK   = NG / 128;
    extern __shared__ char smem[];

    const int e = blockIdx.z;
    const int count = g_cnt[e];
    const int mt = blockIdx.y;
    const int m0 = mt * 128;
    if (m0 >= count) return;
    const int kz = (int)blockIdx.x / NBLK;
    const int n0 = ((int)blockIdx.x % NBLK) * 128;
    const int kc0 = kz * NCHUNK;
    const int tid = threadIdx.x;
    const int wid = tid >> 5, lane = tid & 31;
    const int warp_m = wid & 1;       // 0..1 -> 64-row block
    const int warp_n = wid >> 1;      // 0..1 -> 64-col block
    const uint32_t sbase = smem_u32(smem);

    int*   rows_s  = (int*)(smem + OFF_ROWS);
    float* probs_s = (float*)(smem + OFF_PROBS);
    if (PHASE2) {
        int m = m0 + tid;
        int idx = e * N_TOK + (m < count ? m : count - 1);
        rows_s[tid]  = g_list[idx];
        probs_s[tid] = g_listp[idx];
    }
    if (tid == 0) {
        mbar_init(sbase + OFF_MBAR + 0, 1);
        mbar_init(sbase + OFF_MBAR + 8, 1);
        mbar_init(sbase + OFF_MBAR + 16, 1);
    }
    __syncthreads();

    // Chunk-contiguous packed sources
    const __half* Ap = (PHASE2 ? g_hp : g_xp)
                     + (((size_t)e * MT_MAX + mt) * KCH + kc0) * 8192;   // 8192 elem / chunk
    const __half* Bp = (PHASE2 ? g_w2t : g_w1t)
                     + (((size_t)e * KCH + kc0) * (size_t)NG + n0) * 64;

    auto issue = [&](int c) {
        const uint32_t mb = sbase + OFF_MBAR + (uint32_t)(c % 3) * 8;
        const uint32_t st = sbase + OFF_BUF + (uint32_t)(c % 3) * STAGE_SZ;
        mbar_expect(mb, 32768);
        tma_bulk(st,         Ap + (size_t)c * 8192,            16384, mb);
        tma_bulk(st + B_OFF, Bp + (size_t)c * (size_t)NG * 64, 16384, mb);
    };
    if (tid == 0) {
        issue(0);
        if (NCHUNK > 1) issue(1);
    }

    const int a_r  = lane & 15;
    const int a_kb = lane >> 4;
    const int b_r  = (lane & 7) + ((lane >> 4) << 3);
    const int b_kb = (lane >> 3) & 1;

    float acc[4][8][4];
#pragma unroll
    for (int i = 0; i < 4; i++)
#pragma unroll
        for (int j = 0; j < 8; j++)
#pragma unroll
            for (int q = 0; q < 4; q++) acc[i][j][q] = 0.0f;

    for (int c = 0; c < NCHUNK; c++) {
        const int s = c % 3;
        mbar_wait(sbase + OFF_MBAR + (uint32_t)s * 8, (uint32_t)((c / 3) & 1));
        __syncthreads();   // all warps done with chunk c-1; safe to refill its stage
        if (tid == 0 && c + 2 < NCHUNK) issue(c + 2);

        const uint32_t sA = sbase + OFF_BUF + (uint32_t)s * STAGE_SZ;
        const uint32_t sB = sA + B_OFF;

#pragma unroll
        for (int ks = 0; ks < 4; ks++) {
            uint32_t ah[4][4], bh[8][2];
#pragma unroll
            for (int mf = 0; mf < 4; mf++) {
                int row = warp_m * 64 + mf * 16 + a_r;
                uint32_t off = (uint32_t)(row * 128 + (((2 * ks + a_kb) ^ (row & 7)) << 4));
                ldsm4(ah[mf][0], ah[mf][1], ah[mf][2], ah[mf][3], sA + off);
            }
#pragma unroll
            for (int np = 0; np < 4; np++) {
                int row = warp_n * 64 + np * 16 + b_r;
                uint32_t off = (uint32_t)(row * 128 + (((2 * ks + b_kb) ^ (row & 7)) << 4));
                ldsm4(bh[2 * np][0], bh[2 * np][1], bh[2 * np + 1][0], bh[2 * np + 1][1], sB + off);
            }
#pragma unroll
            for (int mf = 0; mf < 4; mf++)
#pragma unroll
                for (int nf = 0; nf < 8; nf++) mma16816(acc[mf][nf], ah[mf], bh[nf]);
        }
    }

    // ---- epilogue ----
#pragma unroll
    for (int mf = 0; mf < 4; mf++) {
#pragma unroll
        for (int rr = 0; rr < 2; rr++) {
            const int row = warp_m * 64 + mf * 16 + (lane >> 2) + rr * 8;   // 0..127
            const int m = m0 + row;
            if (m >= count) continue;
            if (!PHASE2) {
                // write h (gelu) into g_hp packed layout for GEMM2
#pragma unroll
                for (int nf = 0; nf < 8; nf++) {
                    const int cp = n0 + warp_n * 64 + nf * 8 + 2 * (lane & 3);
                    float h0 = acc[mf][nf][rr * 2 + 0] + bias[(size_t)e * NG + cp];
                    float h1 = acc[mf][nf][rr * 2 + 1] + bias[(size_t)e * NG + cp + 1];
                    h0 = 0.5f * h0 * (1.0f + erff(h0 * 0.70710678118654752f));
                    h1 = 0.5f * h1 * (1.0f + erff(h1 * 0.70710678118654752f));
                    const int kc2 = cp >> 6, g = (cp & 63) >> 3, gi = cp & 7;
                    size_t off = ((((size_t)e * MT_MAX + mt) * (FDIM / 64) + kc2) * 128 + row) * 64
                               + (size_t)((g ^ (row & 7)) * 8 + gi);
                    *(__half2*)(g_hp + off) = __floats2half2_rn(h0, h1);
                }
            } else {
                const int pk = rows_s[row];
                const int tok = pk >> 1;
                const float prob = probs_s[row];
                float* orow = out + (size_t)tok * DIM;
#pragma unroll
                for (int nf = 0; nf < 8; nf++) {
#pragma unroll
                    for (int jj = 0; jj < 2; jj++) {
                        const int col = n0 + warp_n * 64 + nf * 8 + 2 * (lane & 3) + jj;
                        float v = acc[mf][nf][rr * 2 + jj];
                        if (kz == 0) v += bias[(size_t)e * NG + col];
                        atomicAdd(orow + col, v * prob);
                    }
                }
            }
        }
    }
}

// ---------------------------------------------------------------------------
__global__ void finalize_kernel(float* __restrict__ out, int out_size) {
    if (out_size <= N_TOK * DIM) return;
    float s = 0.0f;
#pragma unroll
    for (int e = 0; e < NEXP; e++) s += g_tpe[e];
    float loss = 0.0f;
#pragma unroll
    for (int e = 0; e < NEXP; e++)
        loss += g_tpe[e] / (s + 1e-8f) * (g_psum[e] / (float)N_TOK);
    loss *= (float)NEXP;
    out[N_TOK * DIM] = loss;
}

// ---------------------------------------------------------------------------
extern "C" void kernel_launch(void* const* d_in, const int* in_sizes, int n_in,
                              void* d_out, int out_size) {
    const float* x   = (const float*)d_in[0];
    const float* gw  = (const float*)d_in[1];
    const float* w1  = (const float*)d_in[2];
    const float* b1  = (const float*)d_in[3];
    const float* w2  = (const float*)d_in[4];
    const float* b2  = (const float*)d_in[5];
    float* out = (float*)d_out;

    cudaFuncSetAttribute(moe_gemm<DIM, FDIM, false, 1>,
                         cudaFuncAttributeMaxDynamicSharedMemorySize, SMEM_BYTES);
    cudaFuncSetAttribute(moe_gemm<FDIM, DIM, true, 4>,
                         cudaFuncAttributeMaxDynamicSharedMemorySize, SMEM_BYTES);

    zero_kernel<<<((out_size >> 2) + 255) / 256, 256>>>(out, out_size);
    gate_kernel<<<N_TOK, 128>>>(x, gw);
    convert_w_kernel<<<16384, 256>>>(w1, w2);
    moe_gemm<DIM, FDIM, false, 1><<<dim3(FDIM / 128, MT_MAX, NEXP), 128, SMEM_BYTES>>>(b1, out);
    moe_gemm<FDIM, DIM, true, 4><<<dim3(4 * DIM / 128, MT_MAX, NEXP), 128, SMEM_BYTES>>>(b2, out);
    finalize_kernel<<<1, 1>>>(out, out_size);
}